// round 1
// baseline (speedup 1.0000x reference)
#include <cuda_runtime.h>

#define BB 4
#define NN 1024
#define INF 256
#define OUTF 256
#define NH 8
#define HID 32
#define BN (BB*NN)

// Scratch (allocation-free: __device__ globals)
__device__ float g_buf[BN*OUTF];    // g = h @ W              (4 MB)
__device__ float gs_buf[BN*OUTF];   // g~ = g / s[j,h]        (4 MB)
__device__ float el_buf[BN*NH];     // <g, attn_w[:32]>
__device__ float er_buf[BN*NH];     // <g, attn_w[32:]>

// ---------------------------------------------------------------------------
// K1: g = X @ W  (X:[4096,256], W:[256,256]) + el/er epilogue.
// Block: 16 rows x 256 cols, 256 threads (thread t = column t).
// Warp w == head w in the epilogue (cols 32w..32w+31).
// ---------------------------------------------------------------------------
__global__ __launch_bounds__(256) void k_gemm(const float* __restrict__ X,
                                              const float* __restrict__ W,
                                              const float* __restrict__ aw) {
    __shared__ float Xs[16][33];
    const int t = threadIdx.x;
    const int row0 = blockIdx.x * 16;

    float acc[16];
#pragma unroll
    for (int r = 0; r < 16; r++) acc[r] = 0.f;

    for (int k0 = 0; k0 < INF; k0 += 32) {
#pragma unroll
        for (int i = t; i < 512; i += 256) {
            int r = i >> 5, kk = i & 31;
            Xs[r][kk] = X[(row0 + r) * INF + k0 + kk];
        }
        __syncthreads();
#pragma unroll
        for (int kk = 0; kk < 32; kk++) {
            float wv = __ldg(&W[(k0 + kk) * OUTF + t]);
#pragma unroll
            for (int r = 0; r < 16; r++) acc[r] += Xs[r][kk] * wv;
        }
        __syncthreads();
    }

    const int lane = t & 31;
    const int hh = t >> 5;
    const float awl = aw[lane];
    const float awr = aw[32 + lane];
#pragma unroll
    for (int r = 0; r < 16; r++) {
        g_buf[(row0 + r) * OUTF + t] = acc[r];
        float pl = acc[r] * awl;
        float pr = acc[r] * awr;
#pragma unroll
        for (int off = 16; off; off >>= 1) {
            pl += __shfl_xor_sync(0xffffffffu, pl, off);
            pr += __shfl_xor_sync(0xffffffffu, pr, off);
        }
        if (lane == 0) {
            el_buf[(row0 + r) * NH + hh] = pl;
            er_buf[(row0 + r) * NH + hh] = pr;
        }
    }
}

// ---------------------------------------------------------------------------
// K2: s[b,j,h] = sum_i adj[b,i,j] * exp(leaky(el[b,i,h] + er[b,j,h]))
//     then gs[b,j,h,:] = g[b,j,h,:] / s[b,j,h].
// Block: (b, 32-wide j tile). Threads: warp = i-group (8), lane = j_local.
// adj[b,i,j0+lane] is coalesced per warp per i.
// ---------------------------------------------------------------------------
__global__ __launch_bounds__(256) void k_colsum(const float* __restrict__ adj) {
    __shared__ float er_s[32][9];
    __shared__ float ssum[8][32][8];
    __shared__ float c_s[32][8];
    const int t = threadIdx.x;
    const int b = blockIdx.x >> 5;
    const int j0 = (blockIdx.x & 31) * 32;

    {   // stage er for the 32 j's
        int jl = t >> 3, h2 = t & 7;
        er_s[jl][h2] = er_buf[(b * NN + j0 + jl) * NH + h2];
    }
    __syncthreads();

    const int jl = t & 31;
    const int ig = t >> 5;
    float ers[8];
#pragma unroll
    for (int h2 = 0; h2 < 8; h2++) ers[h2] = er_s[jl][h2];

    float acc[8];
#pragma unroll
    for (int h2 = 0; h2 < 8; h2++) acc[h2] = 0.f;

    const float* adjcol = adj + (size_t)b * NN * NN + j0 + jl;
    for (int i = ig; i < NN; i += 8) {
        float a = __ldg(adjcol + (size_t)i * NN);
        const float4* el4 = reinterpret_cast<const float4*>(el_buf + (b * NN + i) * NH);
        float4 e0 = __ldg(&el4[0]);
        float4 e1 = __ldg(&el4[1]);
        float ev[8] = {e0.x, e0.y, e0.z, e0.w, e1.x, e1.y, e1.z, e1.w};
#pragma unroll
        for (int h2 = 0; h2 < 8; h2++) {
            float e = ev[h2] + ers[h2];
            float lk = fmaxf(e, 0.2f * e);       // leaky relu
            acc[h2] += a * __expf(lk);           // adj is exactly 0.0 or 1.0
        }
    }
#pragma unroll
    for (int h2 = 0; h2 < 8; h2++) ssum[ig][jl][h2] = acc[h2];
    __syncthreads();

    {   // reduce over the 8 i-groups -> c = 1/s
        int jl2 = t >> 3, h2 = t & 7;
        float s = 0.f;
#pragma unroll
        for (int igg = 0; igg < 8; igg++) s += ssum[igg][jl2][h2];
        c_s[jl2][h2] = 1.0f / s;
    }
    __syncthreads();

    // gs = c * g for this j tile (coalesced)
    for (int idx = t; idx < 32 * OUTF; idx += 256) {
        int jl2 = idx >> 8, col = idx & 255, h2 = col >> 5;
        int gi = (b * NN + j0 + jl2) * OUTF + col;
        gs_buf[gi] = c_s[jl2][h2] * g_buf[gi];
    }
}

// ---------------------------------------------------------------------------
// K3: out[b,i,h,:] = sum_j adj[b,i,j]*exp(leaky(el_i+er_j)) * gs[b,j,h,:]
// Block: (b, 32-wide i tile). Chunk j by 32.
// Per chunk: stage gs tile (float4), adj tile, compute 32x8x32 weight tile in
// smem (exactly one exp per (i,j,h)), then float4-vectorized FMA sweep.
// FMA mapping: t -> (iseg = t>>6, h2 = (t>>3)&7, q = t&7); thread owns
// rows iseg*8..+8, head h2, d = 4q..4q+3 (float4 accumulators).
// ---------------------------------------------------------------------------
struct SmemK3 {
    float4 Gs4[32][64];     // gs tile, [jj][h*8+q]          32 KB
    float  Wgt[32][8][33];  // weights, [il][h][jj] padded   33.8 KB
    float  adj_s[32][32];   //                               4 KB
    float  el_s[32][8];
    float  er_s[32][8];
};

__global__ __launch_bounds__(256) void k_agg(const float* __restrict__ adj,
                                             float* __restrict__ out) {
    extern __shared__ char smraw[];
    SmemK3& sm = *reinterpret_cast<SmemK3*>(smraw);
    const int t = threadIdx.x;
    const int b = blockIdx.x >> 5;
    const int i0 = (blockIdx.x & 31) * 32;

    {   // el for this i tile (constant across chunks)
        int il = t >> 3, h2 = t & 7;
        sm.el_s[il][h2] = el_buf[(b * NN + i0 + il) * NH + h2];
    }

    const int h2 = (t >> 3) & 7;   // FMA-loop mapping
    const int q = t & 7;
    const int iseg = t >> 6;
    const int cjj = t & 31;        // weight-compute mapping
    const int ch = t >> 5;

    float4 acc[8];
#pragma unroll
    for (int r = 0; r < 8; r++) acc[r] = make_float4(0.f, 0.f, 0.f, 0.f);

    const float4* gs4 = reinterpret_cast<const float4*>(gs_buf);

    for (int j0 = 0; j0 < NN; j0 += 32) {
        __syncthreads();   // smem reuse barrier (also covers el_s on first iter)
        {
            int jl = t >> 3, hh = t & 7;
            sm.er_s[jl][hh] = er_buf[(b * NN + j0 + jl) * NH + hh];
        }
#pragma unroll
        for (int idx = t; idx < 1024; idx += 256) {
            int il = idx >> 5, jj = idx & 31;
            sm.adj_s[il][jj] = adj[(size_t)(b * NN + i0 + il) * NN + j0 + jj];
        }
#pragma unroll
        for (int v = t; v < 2048; v += 256) {
            int jj = v >> 6, c4 = v & 63;
            sm.Gs4[jj][c4] = gs4[(size_t)(b * NN + j0 + jj) * 64 + c4];
        }
        __syncthreads();

        // weight tile: one exp per (il, h, jj)
        {
            float erv = sm.er_s[cjj][ch];
#pragma unroll
            for (int il = 0; il < 32; il++) {
                float e = sm.el_s[il][ch] + erv;
                float lk = fmaxf(e, 0.2f * e);
                sm.Wgt[il][ch][cjj] = sm.adj_s[il][cjj] * __expf(lk);
            }
        }
        __syncthreads();

        // FMA sweep: 8 rows x 32 j x float4 per thread
#pragma unroll 4
        for (int jj = 0; jj < 32; jj++) {
            float4 gv = sm.Gs4[jj][h2 * 8 + q];
#pragma unroll
            for (int il = 0; il < 8; il++) {
                float w = sm.Wgt[iseg * 8 + il][h2][jj];
                acc[il].x += w * gv.x;
                acc[il].y += w * gv.y;
                acc[il].z += w * gv.z;
                acc[il].w += w * gv.w;
            }
        }
    }

    float4* out4 = reinterpret_cast<float4*>(out);
#pragma unroll
    for (int il = 0; il < 8; il++) {
        int i = i0 + iseg * 8 + il;
        out4[(size_t)(b * NN + i) * 64 + h2 * 8 + q] = acc[il];
    }
}

// ---------------------------------------------------------------------------
extern "C" void kernel_launch(void* const* d_in, const int* in_sizes, int n_in,
                              void* d_out, int out_size) {
    const float* h_in  = (const float*)d_in[0];   // [4,1024,256]
    const float* adj   = (const float*)d_in[1];   // [4,1024,1024,1]
    const float* W     = (const float*)d_in[2];   // [256,256]
    const float* aw    = (const float*)d_in[3];   // [64]
    float* out = (float*)d_out;                   // [4,1024,256]

    static bool attr_set = false;
    if (!attr_set) {
        cudaFuncSetAttribute(k_agg, cudaFuncAttributeMaxDynamicSharedMemorySize,
                             (int)sizeof(SmemK3));
        attr_set = true;
    }

    k_gemm<<<BN / 16, 256>>>(h_in, W, aw);
    k_colsum<<<(BB * NN) / 32, 256>>>(adj);
    k_agg<<<(BB * NN) / 32, 256, sizeof(SmemK3)>>>(adj, out);
}

// round 2
// speedup vs baseline: 1.3987x; 1.3987x over previous
#include <cuda_runtime.h>

#define BB 4
#define NN 1024
#define INF 256
#define OUTF 256
#define NH 8
#define BN (BB*NN)

// ---------------- scratch (allocation-free) ----------------
__device__ float g_buf[BN*OUTF];   // g = h @ W                       (4 MB)
__device__ float Lbuf[BN*16];      // per row: [exp(el_h) x8, exp(.2el_h) x8]
__device__ float Rbuf[BN*16];      // per row: [exp(er_h) x8, exp(.2er_h) x8]
__device__ float c_buf[BN*NH];     // 1/s[b,j,h]

// packed f32x2 helpers
__device__ __forceinline__ unsigned long long pack2(float lo, float hi) {
    unsigned long long r;
    asm("mov.b64 %0, {%1, %2};" : "=l"(r) : "f"(lo), "f"(hi));
    return r;
}
__device__ __forceinline__ void ffma2(unsigned long long& d, unsigned long long a,
                                      unsigned long long b) {
    asm("fma.rn.f32x2 %0, %1, %2, %0;" : "+l"(d) : "l"(a), "l"(b));
}
union U2 { unsigned long long u; float2 f; };

// ---------------------------------------------------------------------------
// K1: g = X @ W.  64x64 tile, 256 threads, 4x4 micro-tile, f32x2 FMAs.
// X duplicated {x,x} in smem so LDS.128 yields ready-packed operands.
// ---------------------------------------------------------------------------
__global__ __launch_bounds__(256) void k_gemm(const float* __restrict__ X,
                                              const float* __restrict__ W) {
    __shared__ __align__(16) float2 Xs2[16][64];  // [kk][row] duplicated
    __shared__ __align__(16) float  Ws [16][64];  // [kk][col]
    const int t = threadIdx.x;
    const int row0 = (blockIdx.x >> 2) * 64;
    const int cb   = (blockIdx.x & 3) * 64;
    const int tx = t & 15, ty = t >> 4;
    const int r0 = ty * 4, c0 = tx * 4;

    unsigned long long acc[4][2];
#pragma unroll
    for (int r = 0; r < 4; r++) { acc[r][0] = 0ull; acc[r][1] = 0ull; }

    const int lr = t >> 2, lk4 = (t & 3) * 4;   // X-load role
    const int wk = t >> 4, wc = (t & 15) * 4;   // W-load role

    for (int k0 = 0; k0 < INF; k0 += 16) {
        float4 xv = *reinterpret_cast<const float4*>(&X[(row0 + lr) * INF + k0 + lk4]);
        float4 wv = *reinterpret_cast<const float4*>(&W[(k0 + wk) * OUTF + cb + wc]);
        __syncthreads();
        Xs2[lk4 + 0][lr] = make_float2(xv.x, xv.x);
        Xs2[lk4 + 1][lr] = make_float2(xv.y, xv.y);
        Xs2[lk4 + 2][lr] = make_float2(xv.z, xv.z);
        Xs2[lk4 + 3][lr] = make_float2(xv.w, xv.w);
        *reinterpret_cast<float4*>(&Ws[wk][wc]) = wv;
        __syncthreads();
#pragma unroll
        for (int kk = 0; kk < 16; kk++) {
            const ulonglong2* xp = reinterpret_cast<const ulonglong2*>(&Xs2[kk][r0]);
            ulonglong2 xa = xp[0], xb = xp[1];
            ulonglong2 wv2 = *reinterpret_cast<const ulonglong2*>(&Ws[kk][c0]);
            ffma2(acc[0][0], xa.x, wv2.x); ffma2(acc[0][1], xa.x, wv2.y);
            ffma2(acc[1][0], xa.y, wv2.x); ffma2(acc[1][1], xa.y, wv2.y);
            ffma2(acc[2][0], xb.x, wv2.x); ffma2(acc[2][1], xb.x, wv2.y);
            ffma2(acc[3][0], xb.y, wv2.x); ffma2(acc[3][1], xb.y, wv2.y);
        }
    }
#pragma unroll
    for (int r = 0; r < 4; r++) {
        U2 a; U2 b; a.u = acc[r][0]; b.u = acc[r][1];
        float4 o = make_float4(a.f.x, a.f.y, b.f.x, b.f.y);
        *reinterpret_cast<float4*>(&g_buf[(row0 + r0 + r) * OUTF + cb + c0]) = o;
    }
}

// ---------------------------------------------------------------------------
// K_elr: per (b,n): el_h = <g_row[h], aw[:32]>, er_h = <g_row[h], aw[32:]>,
// store {exp(el), exp(.2 el)} and {exp(er), exp(.2 er)}. One warp per row.
// ---------------------------------------------------------------------------
__global__ __launch_bounds__(256) void k_elr(const float* __restrict__ aw) {
    const int t = threadIdx.x, wid = t >> 5, l = t & 31;
    const int row = blockIdx.x * 8 + wid;

    const float4* g4 = reinterpret_cast<const float4*>(&g_buf[row * OUTF + l * 8]);
    float4 v0 = g4[0], v1 = g4[1];
    const float4* awp = reinterpret_cast<const float4*>(aw);
    int hb = (l & 3) * 2;                 // aw float4 index base within head
    float4 a0 = awp[hb], a1 = awp[hb + 1];          // el weights
    float4 b0 = awp[8 + hb], b1 = awp[8 + hb + 1];  // er weights

    float el = v0.x*a0.x + v0.y*a0.y + v0.z*a0.z + v0.w*a0.w
             + v1.x*a1.x + v1.y*a1.y + v1.z*a1.z + v1.w*a1.w;
    float er = v0.x*b0.x + v0.y*b0.y + v0.z*b0.z + v0.w*b0.w
             + v1.x*b1.x + v1.y*b1.y + v1.z*b1.z + v1.w*b1.w;
    el += __shfl_xor_sync(0xffffffffu, el, 1);
    el += __shfl_xor_sync(0xffffffffu, el, 2);
    er += __shfl_xor_sync(0xffffffffu, er, 1);
    er += __shfl_xor_sync(0xffffffffu, er, 2);

    int src = 4 * (l & 7);
    float elh = __shfl_sync(0xffffffffu, el, src);
    float erh = __shfl_sync(0xffffffffu, er, src);
    bool isEN = (l & 15) >> 3;
    if (l < 16) Lbuf[row * 16 + l]        = __expf(isEN ? 0.2f * elh : elh);
    else        Rbuf[row * 16 + (l - 16)] = __expf(isEN ? 0.2f * erh : erh);
}

// ---------------------------------------------------------------------------
// K2: c[b,j,h] = 1 / sum_i adj[b,i,j]*wexp(i,j,h)
// wexp = (EPl*EPr >= 1) ? EPl*EPr : ENl*ENr      (no MUFU in the N^2 loop)
// ---------------------------------------------------------------------------
__global__ __launch_bounds__(256) void k_c(const float* __restrict__ adj) {
    __shared__ float ssum[8][32][8];
    const int t = threadIdx.x;
    const int b = blockIdx.x >> 5;
    const int j0 = (blockIdx.x & 31) * 32;
    const int jl = t & 31, ig = t >> 5;

    const float4* rrow = reinterpret_cast<const float4*>(&Rbuf[(b * NN + j0 + jl) * 16]);
    float4 rp0 = rrow[0], rp1 = rrow[1], rn0 = rrow[2], rn1 = rrow[3];
    float EPr[8] = {rp0.x, rp0.y, rp0.z, rp0.w, rp1.x, rp1.y, rp1.z, rp1.w};
    float ENr[8] = {rn0.x, rn0.y, rn0.z, rn0.w, rn1.x, rn1.y, rn1.z, rn1.w};

    float acc[8];
#pragma unroll
    for (int h = 0; h < 8; h++) acc[h] = 0.f;

    const float* adjcol = adj + (size_t)b * NN * NN + j0 + jl;
    for (int i = ig; i < NN; i += 8) {
        float a = __ldg(adjcol + (size_t)i * NN);
        const float4* lr = reinterpret_cast<const float4*>(&Lbuf[(b * NN + i) * 16]);
        float4 lp0 = __ldg(&lr[0]), lp1 = __ldg(&lr[1]);
        float4 ln0 = __ldg(&lr[2]), ln1 = __ldg(&lr[3]);
        float EPl[8] = {lp0.x, lp0.y, lp0.z, lp0.w, lp1.x, lp1.y, lp1.z, lp1.w};
        float ENl[8] = {ln0.x, ln0.y, ln0.z, ln0.w, ln1.x, ln1.y, ln1.z, ln1.w};
#pragma unroll
        for (int h = 0; h < 8; h++) {
            float p = EPl[h] * EPr[h];
            float q = ENl[h] * ENr[h];
            float w = (p >= 1.0f) ? p : q;
            acc[h] = fmaf(a, w, acc[h]);
        }
    }
#pragma unroll
    for (int h = 0; h < 8; h++) ssum[ig][jl][h] = acc[h];
    __syncthreads();

    {
        int jl2 = t >> 3, h = t & 7;
        float s = 0.f;
#pragma unroll
        for (int g = 0; g < 8; g++) s += ssum[g][jl2][h];
        c_buf[(b * NN + j0 + jl2) * NH + h] = 1.0f / s;
    }
}

// ---------------------------------------------------------------------------
// K3: out[b,i,h,:] = sum_j adj*wexp*c[j,h] * g[b,j,h,:]
// Block: 16 i-rows x all 256 d.  j chunks of 32.  Weight tile in smem,
// f32x2 FMA sweep; warp == one head so all weight/g LDS are contiguous.
// ---------------------------------------------------------------------------
struct SmemAgg {
    float4 Gs4[32][64];      // g tile [jj][h*8+q]         32 KB
    float  Wgt[8][32][16];   // [h][jj][il]                16 KB
    float  adj_s[16][32];    //                             2 KB
    float  Ltile[16][16];    // staged Lbuf rows            1 KB
};

__global__ __launch_bounds__(256) void k_agg(const float* __restrict__ adj,
                                             float* __restrict__ out) {
    extern __shared__ char smraw[];
    SmemAgg& sm = *reinterpret_cast<SmemAgg*>(smraw);
    const int t = threadIdx.x;
    const int b = blockIdx.x >> 6;
    const int i0 = (blockIdx.x & 63) * 16;

    {   // stage L rows for this i tile (constant across chunks)
        int il = t >> 4, c = t & 15;
        sm.Ltile[il][c] = Lbuf[(b * NN + i0 + il) * 16 + c];
    }

    const int cjj = t & 31, ch = t >> 5;          // weight-compute role
    const int h2 = t >> 5, iseg = (t >> 3) & 3, q = t & 7;  // FMA role

    unsigned long long acc2[4][2];
#pragma unroll
    for (int r = 0; r < 4; r++) { acc2[r][0] = 0ull; acc2[r][1] = 0ull; }

    const float4* g4 = reinterpret_cast<const float4*>(g_buf);

    for (int j0 = 0; j0 < NN; j0 += 32) {
        // per-chunk j-side scalars (gmem, coalesced-ish, tiny)
        float cc = c_buf[(b * NN + j0 + cjj) * NH + ch];
        float Rp = Rbuf[(b * NN + j0 + cjj) * 16 + ch] * cc;
        float Rn = Rbuf[(b * NN + j0 + cjj) * 16 + 8 + ch] * cc;

        __syncthreads();
#pragma unroll
        for (int m = 0; m < 2; m++) {
            int idx = t + m * 256;
            int il = idx >> 5, jj = idx & 31;
            sm.adj_s[il][jj] = adj[(size_t)(b * NN + i0 + il) * NN + j0 + jj];
        }
#pragma unroll
        for (int m = 0; m < 8; m++) {
            int v = t + m * 256;
            int jj = v >> 6, c4 = v & 63;
            sm.Gs4[jj][c4] = g4[(size_t)(b * NN + j0 + jj) * 64 + c4];
        }
        __syncthreads();

        // weight tile: w = adj * c * ((EPl*EPr>=1)? EPl*EPr : ENl*ENr)
#pragma unroll
        for (int il = 0; il < 16; il++) {
            float p = sm.Ltile[il][ch] * Rp;       // scaled by c
            float qq = sm.Ltile[il][8 + ch] * Rn;  // scaled by c
            float w = (p >= cc) ? p : qq;          // p/c >= 1
            sm.Wgt[ch][cjj][il] = sm.adj_s[il][cjj] * w;
        }
        __syncthreads();

        // FMA sweep
#pragma unroll 4
        for (int jj = 0; jj < 32; jj++) {
            ulonglong2 gv = *reinterpret_cast<const ulonglong2*>(&sm.Gs4[jj][h2 * 8 + q]);
            float4 wv = *reinterpret_cast<const float4*>(&sm.Wgt[h2][jj][iseg * 4]);
            unsigned long long w0 = pack2(wv.x, wv.x);
            unsigned long long w1 = pack2(wv.y, wv.y);
            unsigned long long w2 = pack2(wv.z, wv.z);
            unsigned long long w3 = pack2(wv.w, wv.w);
            ffma2(acc2[0][0], w0, gv.x); ffma2(acc2[0][1], w0, gv.y);
            ffma2(acc2[1][0], w1, gv.x); ffma2(acc2[1][1], w1, gv.y);
            ffma2(acc2[2][0], w2, gv.x); ffma2(acc2[2][1], w2, gv.y);
            ffma2(acc2[3][0], w3, gv.x); ffma2(acc2[3][1], w3, gv.y);
        }
    }

    float4* out4 = reinterpret_cast<float4*>(out);
#pragma unroll
    for (int il = 0; il < 4; il++) {
        int i = i0 + iseg * 4 + il;
        U2 a, bb; a.u = acc2[il][0]; bb.u = acc2[il][1];
        out4[(size_t)(b * NN + i) * 64 + h2 * 8 + q] =
            make_float4(a.f.x, a.f.y, bb.f.x, bb.f.y);
    }
}

// ---------------------------------------------------------------------------
extern "C" void kernel_launch(void* const* d_in, const int* in_sizes, int n_in,
                              void* d_out, int out_size) {
    const float* h_in = (const float*)d_in[0];   // [4,1024,256]
    const float* adj  = (const float*)d_in[1];   // [4,1024,1024,1]
    const float* W    = (const float*)d_in[2];   // [256,256]
    const float* aw   = (const float*)d_in[3];   // [64]
    float* out = (float*)d_out;

    static bool attr_set = false;
    if (!attr_set) {
        cudaFuncSetAttribute(k_agg, cudaFuncAttributeMaxDynamicSharedMemorySize,
                             (int)sizeof(SmemAgg));
        attr_set = true;
    }

    k_gemm<<<256, 256>>>(h_in, W);
    k_elr<<<BN / 8, 256>>>(aw);
    k_c<<<(BB * NN) / 32, 256>>>(adj);
    k_agg<<<(BB * NN) / 16, 256, sizeof(SmemAgg)>>>(adj, out);
}